// round 4
// baseline (speedup 1.0000x reference)
#include <cuda_runtime.h>

// out[c] = dequant(quant(x[c])) with channel c's quant group = inv[c]>>7.
// One block processes 4 rows of 4096 floats; perm/inv indices are identical
// across rows and live in registers. Param table is bank-replicated
// (entry g at [g*32+lane]) so all pass-B lookups are conflict-free.

#define ROW_C    4096
#define NTHREADS 1024
#define ROWS_PB  4
#define Q_MAX    15.0f
#define EPS      1e-5f

__global__ __launch_bounds__(NTHREADS, 2)
void tpq_kernel(const float4* __restrict__ x4,
                const int*    __restrict__ perm,
                const int4*   __restrict__ inv4,
                float4*       __restrict__ out4)
{
    __shared__ float4 sx4[ROW_C / 4];        // 16 KB
    __shared__ float  s_inv [32 * 32];       // 4 KB, bank-replicated
    __shared__ float  s_scl [32 * 32];       // 4 KB
    __shared__ float  s_bse [32 * 32];       // 4 KB

    const int tid  = threadIdx.x;
    const int warp = tid >> 5;
    const int lane = tid & 31;

    // ---- per-block constants: indices identical for every row ----
    const int4 pinv = __ldg(&inv4[tid]);               // groups of my 4 channels
    const int  gx = pinv.x >> 7, gy = pinv.y >> 7,
               gz = pinv.z >> 7, gw = pinv.w >> 7;
    int pperm[4];
    #pragma unroll
    for (int i = 0; i < 4; ++i)
        pperm[i] = __ldg(&perm[warp * 128 + lane + 32 * i]);

    const float* sx = (const float*)sx4;
    size_t row4 = (size_t)blockIdx.x * ROWS_PB * (ROW_C / 4);

    float4 a = x4[row4 + tid];                         // prefetch row 0

    #pragma unroll 1
    for (int r = 0; r < ROWS_PB; ++r) {
        sx4[tid] = a;
        __syncthreads();                               // sx ready

        // ---- pass A: warp w reduces min/max of permuted group w ----
        float vmin =  INFINITY, vmax = -INFINITY;
        #pragma unroll
        for (int i = 0; i < 4; ++i) {
            const float val = sx[pperm[i]];            // random LDS (fixed pattern)
            vmin = fminf(vmin, val);
            vmax = fmaxf(vmax, val);
        }
        #pragma unroll
        for (int off = 16; off; off >>= 1) {
            vmin = fminf(vmin, __shfl_xor_sync(0xffffffffu, vmin, off));
            vmax = fmaxf(vmax, __shfl_xor_sync(0xffffffffu, vmax, off));
        }

        float scale, inv_s, base_q;
        if (lane == 0) {
            scale  = fmaxf(vmax - vmin, EPS) / Q_MAX;
            inv_s  = 1.0f / scale;
            base_q = fminf(fmaxf(rintf(-vmin * inv_s), 0.0f), Q_MAX);
        }
        scale  = __shfl_sync(0xffffffffu, scale,  0);
        inv_s  = __shfl_sync(0xffffffffu, inv_s,  0);
        base_q = __shfl_sync(0xffffffffu, base_q, 0);

        // replicate params: group w's value at [w*32 + lane] (bank = lane)
        s_inv[warp * 32 + lane] = inv_s;
        s_scl[warp * 32 + lane] = scale;
        s_bse[warp * 32 + lane] = base_q;
        __syncthreads();                               // table ready

        // ---- pass B: conflict-free table reads (bank = lane) ----
        float4 o;
        {
            const int t = gx * 32 + lane;
            const float b = s_bse[t];
            float q = fminf(fmaxf(rintf(a.x * s_inv[t]) + b, 0.0f), Q_MAX);
            o.x = (q - b) * s_scl[t];
        }
        {
            const int t = gy * 32 + lane;
            const float b = s_bse[t];
            float q = fminf(fmaxf(rintf(a.y * s_inv[t]) + b, 0.0f), Q_MAX);
            o.y = (q - b) * s_scl[t];
        }
        {
            const int t = gz * 32 + lane;
            const float b = s_bse[t];
            float q = fminf(fmaxf(rintf(a.z * s_inv[t]) + b, 0.0f), Q_MAX);
            o.z = (q - b) * s_scl[t];
        }
        {
            const int t = gw * 32 + lane;
            const float b = s_bse[t];
            float q = fminf(fmaxf(rintf(a.w * s_inv[t]) + b, 0.0f), Q_MAX);
            o.w = (q - b) * s_scl[t];
        }
        out4[row4 + tid] = o;

        row4 += ROW_C / 4;
        if (r + 1 < ROWS_PB)
            a = x4[row4 + tid];                        // prefetch next row
        __syncthreads();                               // protect sx/table reuse
    }
}

extern "C" void kernel_launch(void* const* d_in, const int* in_sizes, int n_in,
                              void* d_out, int out_size)
{
    const float4* x4   = (const float4*)d_in[0];
    const int*    perm = (const int*)d_in[1];
    const int4*   inv4 = (const int4*)d_in[2];
    float4*       out4 = (float4*)d_out;

    const int rows = in_sizes[0] / ROW_C;              // 16384
    tpq_kernel<<<rows / ROWS_PB, NTHREADS>>>(x4, perm, inv4, out4);
}

// round 5
// speedup vs baseline: 1.0465x; 1.0465x over previous
#include <cuda_runtime.h>
#include <math_constants.h>

// out[c] = dequant(quant(x[c])) with channel c's quant group = inv[c]>>7.
// Block = 4 rows. Rows are interleaved in smem (s4[c] = 4 rows' values of
// channel c) so ONE random LDS.128 gather serves min/max of 4 rows.
// Channel assignment c = tid + 1024k keeps every global access coalesced and
// every smem access conflict-free. Group params are distributed via a
// bank-replicated float2 table: (inv_scale, scale|base packed in low 4 bits).

#define ROW_C 4096
#define NT    1024
#define RPT   4
#define Q_MAX 15.0f
#define EPS   1e-5f

extern __shared__ float4 smem_dyn[];

__global__ __launch_bounds__(NT)
void tpq_kernel(const float* __restrict__ x,
                const int*   __restrict__ perm,
                const int*   __restrict__ inv,
                float*       __restrict__ out)
{
    float4* s4  = smem_dyn;                       // [4096] float4 = 64 KB
    float2* tab = (float2*)(s4 + ROW_C);          // [RPT][32*16] float2 = 16 KB

    const int t    = threadIdx.x;
    const int warp = t >> 5;
    const int lane = t & 31;
    const int m    = lane & 15;
    const size_t rowbase = (size_t)blockIdx.x * (RPT * ROW_C);

    // ---- load 16 values (4 rows x 4 channels c = t + 1024k), coalesced ----
    float v[RPT][4];
    #pragma unroll
    for (int r = 0; r < RPT; ++r)
        #pragma unroll
        for (int k = 0; k < 4; ++k)
            v[r][k] = x[rowbase + r * ROW_C + t + 1024 * k];

    // ---- per-block index loads (L2-resident) ----
    int g[4];
    #pragma unroll
    for (int k = 0; k < 4; ++k)
        g[k] = __ldg(&inv[t + 1024 * k]) >> 7;
    int pp[4];
    #pragma unroll
    for (int i = 0; i < 4; ++i)
        pp[i] = __ldg(&perm[warp * 128 + lane + 32 * i]);

    // ---- stage interleaved: s4[c] = {r0[c], r1[c], r2[c], r3[c]} ----
    // addr bank_start = (4t)&31: 8 bins x 4 lanes, quarter-warp phases
    // disjoint -> conflict-free STS.128.
    #pragma unroll
    for (int k = 0; k < 4; ++k)
        s4[t + 1024 * k] = make_float4(v[0][k], v[1][k], v[2][k], v[3][k]);
    __syncthreads();

    // ---- pass A: warp w reduces permuted group w for all 4 rows ----
    float mn[RPT], mx[RPT];
    #pragma unroll
    for (int r = 0; r < RPT; ++r) { mn[r] = CUDART_INF_F; mx[r] = -CUDART_INF_F; }

    #pragma unroll
    for (int i = 0; i < 4; ++i) {
        const float4 w4 = s4[pp[i]];              // 1 gather serves 4 rows
        mn[0] = fminf(mn[0], w4.x);  mx[0] = fmaxf(mx[0], w4.x);
        mn[1] = fminf(mn[1], w4.y);  mx[1] = fmaxf(mx[1], w4.y);
        mn[2] = fminf(mn[2], w4.z);  mx[2] = fmaxf(mx[2], w4.z);
        mn[3] = fminf(mn[3], w4.w);  mx[3] = fmaxf(mx[3], w4.w);
    }
    #pragma unroll
    for (int off = 16; off; off >>= 1) {
        #pragma unroll
        for (int r = 0; r < RPT; ++r) {
            mn[r] = fminf(mn[r], __shfl_xor_sync(0xffffffffu, mn[r], off));
            mx[r] = fmaxf(mx[r], __shfl_xor_sync(0xffffffffu, mx[r], off));
        }
    }

    // params; lanes 0-15 write the 16x-replicated table (1 wf per row)
    #pragma unroll
    for (int r = 0; r < RPT; ++r) {
        const float scale = fmaxf(mx[r] - mn[r], EPS) / Q_MAX;
        const float inv_s = 1.0f / scale;
        const float base  = fminf(fmaxf(rintf(-mn[r] * inv_s), 0.0f), Q_MAX);
        // pack integer base (0..15) into scale's low 4 mantissa bits:
        // perturbs only the dequant multiply by <=1.8e-6 rel (no rint impact)
        const unsigned us = (__float_as_uint(scale) & ~15u) | (unsigned)base;
        if (lane < 16)
            tab[r * (32 * 16) + warp * 16 + lane] =
                make_float2(inv_s, __uint_as_float(us));
    }
    __syncthreads();

    // ---- pass B: quantize register values; conflict-free table reads ----
    #pragma unroll
    for (int r = 0; r < RPT; ++r) {
        #pragma unroll
        for (int k = 0; k < 4; ++k) {
            const float2 e = tab[r * (32 * 16) + g[k] * 16 + m];
            const unsigned u = __float_as_uint(e.y);
            const float base = (float)(u & 15u);
            float q = rintf(v[r][k] * e.x);
            q = fminf(fmaxf(q, -base), Q_MAX - base);   // == clip(q+b,0,15)-b
            out[rowbase + r * ROW_C + t + 1024 * k] = q * e.y;
        }
    }
}

extern "C" void kernel_launch(void* const* d_in, const int* in_sizes, int n_in,
                              void* d_out, int out_size)
{
    const float* x    = (const float*)d_in[0];
    const int*   perm = (const int*)d_in[1];
    const int*   inv  = (const int*)d_in[2];
    float*       out  = (float*)d_out;

    const int smem_bytes = ROW_C * sizeof(float4) + RPT * 32 * 16 * sizeof(float2);
    cudaFuncSetAttribute(tpq_kernel,
                         cudaFuncAttributeMaxDynamicSharedMemorySize, smem_bytes);

    const int rows = in_sizes[0] / ROW_C;              // 16384
    tpq_kernel<<<rows / RPT, NT, smem_bytes>>>(x, perm, inv, out);
}

// round 6
// speedup vs baseline: 1.2811x; 1.2242x over previous
#include <cuda_runtime.h>
#include <math_constants.h>

// out[c] = dequant(quant(x[c])) with channel c's quant group = inv[c]>>7.
// Block = 4 rows, interleaved in smem (s4[c] = {r0..r3}[c]) so one random
// LDS.128 serves 4 rows in both the min/max gather and the pass-B reread.
// Param tables are float4-per-group (4 rows) replicated 8x for phase-
// conflict-free LDS.128. __launch_bounds__(1024,2) -> 2 CTAs/SM, 64 warps.

#define ROW_C 4096
#define NT    1024
#define RPT   4
#define Q_MAX 15.0f
#define EPS   1e-5f

extern __shared__ float4 smem_dyn[];

__global__ __launch_bounds__(NT, 2)
void tpq_kernel(const float* __restrict__ x,
                const int*   __restrict__ perm,
                const int*   __restrict__ inv,
                float*       __restrict__ out)
{
    float4* s4      = smem_dyn;                 // [4096] float4 = 64 KB
    float4* tab_inv = s4 + ROW_C;               // [32*8] float4 = 4 KB
    float4* tab_sc  = tab_inv + 32 * 8;         // [32*8] float4 = 4 KB

    const int t    = threadIdx.x;
    const int warp = t >> 5;
    const int lane = t & 31;
    const int m8   = lane & 7;
    const size_t rowbase = (size_t)blockIdx.x * (RPT * ROW_C);

    // ---- stage 4 rows interleaved; coalesced streaming loads ----
    #pragma unroll
    for (int k = 0; k < 4; ++k) {
        const size_t c = rowbase + t + 1024 * k;
        s4[t + 1024 * k] = make_float4(__ldcs(&x[c]),
                                       __ldcs(&x[c + ROW_C]),
                                       __ldcs(&x[c + 2 * ROW_C]),
                                       __ldcs(&x[c + 3 * ROW_C]));
    }

    // perm indices for my warp's group (L2-resident)
    int pp[4];
    #pragma unroll
    for (int i = 0; i < 4; ++i)
        pp[i] = __ldg(&perm[warp * 128 + lane + 32 * i]);
    __syncthreads();

    // ---- pass A: warp w reduces permuted group w for all 4 rows ----
    float mn[RPT], mx[RPT];
    #pragma unroll
    for (int r = 0; r < RPT; ++r) { mn[r] = CUDART_INF_F; mx[r] = -CUDART_INF_F; }

    #pragma unroll
    for (int i = 0; i < 4; ++i) {
        const float4 w4 = s4[pp[i]];            // 1 random gather, 4 rows
        mn[0] = fminf(mn[0], w4.x);  mx[0] = fmaxf(mx[0], w4.x);
        mn[1] = fminf(mn[1], w4.y);  mx[1] = fmaxf(mx[1], w4.y);
        mn[2] = fminf(mn[2], w4.z);  mx[2] = fmaxf(mx[2], w4.z);
        mn[3] = fminf(mn[3], w4.w);  mx[3] = fmaxf(mx[3], w4.w);
    }
    #pragma unroll
    for (int off = 16; off; off >>= 1) {
        #pragma unroll
        for (int r = 0; r < RPT; ++r) {
            mn[r] = fminf(mn[r], __shfl_xor_sync(0xffffffffu, mn[r], off));
            mx[r] = fmaxf(mx[r], __shfl_xor_sync(0xffffffffu, mx[r], off));
        }
    }

    // params (all lanes hold them); lanes 0-7 write the 8x-replicated tables
    {
        float4 iv, sc;
        float* ivp = (float*)&iv;
        float* scp = (float*)&sc;
        #pragma unroll
        for (int r = 0; r < RPT; ++r) {
            const float scale = fmaxf(mx[r] - mn[r], EPS) / Q_MAX;
            const float inv_s = 1.0f / scale;
            const float base  = fminf(fmaxf(rintf(-mn[r] * inv_s), 0.0f), Q_MAX);
            // pack integer base (0..15) into scale's low 4 mantissa bits
            // (perturbs only the final multiply by <=1.8e-6 rel)
            ivp[r] = inv_s;
            scp[r] = __uint_as_float((__float_as_uint(scale) & ~15u) |
                                     (unsigned)base);
        }
        if (lane < 8) {
            tab_inv[warp * 8 + lane] = iv;
            tab_sc [warp * 8 + lane] = sc;
        }
    }

    // group ids for my channels (load late to cut register liveness)
    int g[4];
    #pragma unroll
    for (int k = 0; k < 4; ++k)
        g[k] = __ldg(&inv[t + 1024 * k]) >> 7;
    __syncthreads();

    // ---- pass B: reread staged data, quantize, coalesced stores ----
    #pragma unroll
    for (int k = 0; k < 4; ++k) {
        const float4 d  = s4[t + 1024 * k];               // 4 rows' values
        const float4 iv = tab_inv[g[k] * 8 + m8];         // conflict-free
        const float4 sc = tab_sc [g[k] * 8 + m8];
        const float* dp  = (const float*)&d;
        const float* ivp = (const float*)&iv;
        const float* scp = (const float*)&sc;
        const size_t c = rowbase + t + 1024 * k;
        #pragma unroll
        for (int r = 0; r < RPT; ++r) {
            const float base = (float)(__float_as_uint(scp[r]) & 15u);
            float q = rintf(dp[r] * ivp[r]);
            q = fminf(fmaxf(q, -base), Q_MAX - base);     // == clip(q+b,0,15)-b
            __stcg(&out[c + r * ROW_C], q * scp[r]);
        }
    }
}

extern "C" void kernel_launch(void* const* d_in, const int* in_sizes, int n_in,
                              void* d_out, int out_size)
{
    const float* x    = (const float*)d_in[0];
    const int*   perm = (const int*)d_in[1];
    const int*   inv  = (const int*)d_in[2];
    float*       out  = (float*)d_out;

    const int smem_bytes = ROW_C * sizeof(float4) + 2 * 32 * 8 * sizeof(float4);
    cudaFuncSetAttribute(tpq_kernel,
                         cudaFuncAttributeMaxDynamicSharedMemorySize, smem_bytes);

    const int rows = in_sizes[0] / ROW_C;              // 16384
    tpq_kernel<<<rows / RPT, NT, smem_bytes>>>(x, perm, inv, out);
}